// round 1
// baseline (speedup 1.0000x reference)
#include <cuda_runtime.h>
#include <math.h>

// Problem constants
// B=4, D1=D2=D3=64, CIN=COUT=32, M1=M2=M3=8
// Pipeline (all exact linear algebra, no full FFTs):
//   A[b,m,d2,p,c]  = sum_d3 x[b,m,d2,d3,c] e^{-2pi i p d3/64}            (m<8,p<8)
//   Bs[b,m,n,p,c]  = sum_d2 A[b,m,d2,p,c] e^{-2pi i n d2/64}             (n<8)
//   U1[b,m,n,p,co] = sum_c Bs[b,m,n,p,c] * M_p[c,co]
//       M_p[c,co] = (1/131072) sum_{k,o} e^{-2pi i kc/32} Wsum[p,k,o] e^{+2pi i o co/32}
//       Wsum[p,k,o] = sum_{ij} (w_real+i w_imag)[k,o,i,j,p]
//   V[b,m,n,d3,co] = sum_{p<8} U1 e^{+2pi i p d3/64}
//   y[b,m,d2,d3,co]= Re sum_{n<8} V e^{+2pi i n d2/64}     (m<8; y[:,8:]=0)

#define NB 4
#define ND 64
#define NC 32
#define NM 8

// Scratch (static device globals, allowed)
__device__ float2 g_A   [NB*NM*ND*NM*NC];   // [b][m][d2][p][c]   4 MB
__device__ float2 g_U1  [NB*NM*NM*NM*NC];   // [b][m][n][p][co]   512 KB
__device__ float2 g_Ws  [NM*NC*NC];         // [p][k][o]          64 KB
__device__ float2 g_M   [NM*NC*NC];         // [p][c][co]         64 KB

// ---------------------------------------------------------------------------
// Prep 1: Wsum[p][k][o] = sum_{ij} (wr + i wi)[k][o][i][j][p]
// ---------------------------------------------------------------------------
__global__ void prep_wsum(const float* __restrict__ wr, const float* __restrict__ wi) {
    int t = blockIdx.x * blockDim.x + threadIdx.x;   // 8192 threads
    int p = t & 7;
    int o = (t >> 3) & 31;
    int k = t >> 8;
    float sr = 0.f, si = 0.f;
    int base = (k * 32 + o) * 512 + p;               // w[k][o][i][j][p], p stride 1
    #pragma unroll 8
    for (int ij = 0; ij < 64; ij++) {
        sr += wr[base + ij * 8];
        si += wi[base + ij * 8];
    }
    g_Ws[(p * 32 + k) * 32 + o] = make_float2(sr, si);
}

// ---------------------------------------------------------------------------
// Prep 2: M_p = (1/131072) * IDFT32 o Wsum_p o DFT32  (one block per p)
// ---------------------------------------------------------------------------
__global__ void prep_M() {
    __shared__ float2 tw32[32];
    __shared__ float2 Ws[1024];
    __shared__ float2 P[1024];
    int p = blockIdx.x;
    int t = threadIdx.x;                              // 1024 threads
    if (t < 32) {
        float s, c;
        sincospif(-(float)t / 16.0f, &s, &c);         // e^{-2pi i t/32}
        tw32[t] = make_float2(c, s);
    }
    Ws[t] = g_Ws[p * 1024 + t];
    __syncthreads();
    // P[c][o] = sum_k e^{-2pi i kc/32} * Ws[k][o]
    {
        int o = t & 31, c = t >> 5;
        float2 acc = make_float2(0.f, 0.f);
        #pragma unroll 8
        for (int k = 0; k < 32; k++) {
            float2 e = tw32[(k * c) & 31];
            float2 w = Ws[k * 32 + o];
            acc.x += e.x * w.x - e.y * w.y;
            acc.y += e.x * w.y + e.y * w.x;
        }
        P[c * 32 + o] = acc;
    }
    __syncthreads();
    // M[c][co] = scale * sum_o P[c][o] * e^{+2pi i o co/32}  (= conj of tw32)
    {
        int co = t & 31, c = t >> 5;
        float2 acc = make_float2(0.f, 0.f);
        #pragma unroll 8
        for (int o = 0; o < 32; o++) {
            float2 e = tw32[(o * co) & 31];
            float2 v = P[c * 32 + o];
            acc.x += v.x * e.x + v.y * e.y;   // v * conj(e)
            acc.y += v.y * e.x - v.x * e.y;
        }
        const float scale = 1.0f / 131072.0f;  // 1/(64*64*32)
        g_M[(p * 32 + c) * 32 + co] = make_float2(acc.x * scale, acc.y * scale);
    }
}

// ---------------------------------------------------------------------------
// F1: d3 forward DFT (64 -> 8 modes). One block per (b,m,d2). 2048 blocks.
// ---------------------------------------------------------------------------
__global__ void fwd_d3(const float* __restrict__ x) {
    __shared__ float  xs[2048];
    __shared__ float2 tw[64];
    int t = threadIdx.x;                              // 256
    if (t < 64) {
        float s, c;
        sincospif(-(float)t / 32.0f, &s, &c);         // e^{-2pi i t/64}
        tw[t] = make_float2(c, s);
    }
    int blk = blockIdx.x;                             // (b*8+m)*64 + d2
    int bm = blk >> 6;
    int d2 = blk & 63;
    int b = bm >> 3, m = bm & 7;
    const float4* xin = (const float4*)(x + ((size_t)(b * 64 + m) * 64 + d2) * 2048);
    float4* xs4 = (float4*)xs;
    xs4[t]       = xin[t];
    xs4[t + 256] = xin[t + 256];
    __syncthreads();
    int p = t >> 5, c = t & 31;
    float ar = 0.f, ai = 0.f;
    #pragma unroll 8
    for (int d3 = 0; d3 < 64; d3++) {
        float v = xs[d3 * 32 + c];
        float2 e = tw[(p * d3) & 63];
        ar += v * e.x;
        ai += v * e.y;
    }
    g_A[(size_t)blk * 256 + t] = make_float2(ar, ai);
}

// ---------------------------------------------------------------------------
// F2+F3 fused: d2 forward DFT (64 -> 8 modes) + channel mix via M_p.
// One block per (b,m). 32 blocks, 256 threads.
// dyn smem: tw(64) + Bs(2048) + Ms(8192) float2 = 82432 B
// ---------------------------------------------------------------------------
extern __shared__ float2 sm_f23[];
__global__ void fwd_d2_mix() {
    float2* tw = sm_f23;            // 64
    float2* Bs = sm_f23 + 64;       // [n][p][c] 2048
    float2* Ms = sm_f23 + 64 + 2048;// [p][c][co] 8192
    int t = threadIdx.x;
    int bm = blockIdx.x;
    if (t < 64) {
        float s, c;
        sincospif(-(float)t / 32.0f, &s, &c);
        tw[t] = make_float2(c, s);
    }
    {   // stage M into smem (vectorized)
        const float4* msrc = (const float4*)g_M;
        float4* mdst = (float4*)Ms;
        #pragma unroll
        for (int i = 0; i < 16; i++) mdst[t + i * 256] = msrc[t + i * 256];
    }
    __syncthreads();
    // phase 1: d2 DFT
    int p = t >> 5, c = t & 31;
    float2 acc[8];
    #pragma unroll
    for (int n = 0; n < 8; n++) acc[n] = make_float2(0.f, 0.f);
    const float2* Ab = g_A + (size_t)bm * 16384;      // [d2][p][c]
    for (int d2 = 0; d2 < 64; d2++) {
        float2 a = Ab[d2 * 256 + t];
        #pragma unroll
        for (int n = 0; n < 8; n++) {
            float2 e = tw[(n * d2) & 63];
            acc[n].x += a.x * e.x - a.y * e.y;
            acc[n].y += a.x * e.y + a.y * e.x;
        }
    }
    #pragma unroll
    for (int n = 0; n < 8; n++) Bs[(n * 8 + p) * 32 + c] = acc[n];
    __syncthreads();
    // phase 2: U1[site][co] = sum_c Bs[site][c] * M_p[c][co]
    int co = t & 31, s0 = t >> 5;
    float2* Uo = g_U1 + (size_t)bm * 2048;
    #pragma unroll
    for (int i = 0; i < 8; i++) {
        int site = i * 8 + s0;                        // n*8+p
        int pp = site & 7;
        float2 u = make_float2(0.f, 0.f);
        const float2* Bp = Bs + site * 32;
        const float2* Mp = Ms + pp * 1024 + co;
        #pragma unroll 8
        for (int cc = 0; cc < 32; cc++) {
            float2 bv = Bp[cc];                       // broadcast within warp
            float2 mv = Mp[cc * 32];                  // stride-1 across co
            u.x += bv.x * mv.x - bv.y * mv.y;
            u.y += bv.x * mv.y + bv.y * mv.x;
        }
        Uo[site * 32 + co] = u;
    }
}

// ---------------------------------------------------------------------------
// I1+I2 fused: d3 inverse (8 modes -> 64) + d2 inverse (8 modes -> 64) + Re.
// One block per (b,m,d3tile16). 128 blocks, 256 threads.
// dyn smem: tw(64) + Us(2048) + Vs(4096) float2 = 49664 B
// ---------------------------------------------------------------------------
extern __shared__ float2 sm_inv[];
__global__ void inv_kernel(float* __restrict__ out) {
    float2* tw = sm_inv;              // 64
    float2* Us = sm_inv + 64;         // [n][p][co] 2048
    float2* Vs = sm_inv + 64 + 2048;  // [n][dd][co] 4096
    int t = threadIdx.x;
    int blk = blockIdx.x;             // (b*8+m)*4 + tile
    int bm = blk >> 2;
    int tile = blk & 3;
    int b = bm >> 3, m = bm & 7;
    if (t < 64) {
        float s, c;
        sincospif(-(float)t / 32.0f, &s, &c);         // e^{-2pi i t/64}
        tw[t] = make_float2(c, s);
    }
    {   // stage U1[b][m] slice
        const float4* us = (const float4*)(g_U1 + (size_t)bm * 2048);
        float4* ud = (float4*)Us;
        #pragma unroll
        for (int i = 0; i < 4; i++) ud[t + i * 256] = us[t + i * 256];
    }
    __syncthreads();
    // phase 1: V[n][dd][co] = sum_p Us[n][p][co] * e^{+2pi i p d3/64}
    {
        int co = t & 31, r = t >> 5;
        #pragma unroll
        for (int i = 0; i < 16; i++) {
            int pair = i * 8 + r;                     // (n,dd) in 8x16
            int n = pair >> 4, dd = pair & 15;
            int d3 = tile * 16 + dd;
            float2 acc = make_float2(0.f, 0.f);
            #pragma unroll
            for (int p = 0; p < 8; p++) {
                float2 u = Us[(n * 8 + p) * 32 + co];
                float2 e = tw[(p * d3) & 63];         // use conj => e^{+i}
                acc.x += u.x * e.x + u.y * e.y;
                acc.y += u.y * e.x - u.x * e.y;
            }
            Vs[(n * 16 + dd) * 32 + co] = acc;
        }
    }
    __syncthreads();
    // phase 2: y[d2][d3][co] = sum_n Re(Vs[n][dd][co] * e^{+2pi i n d2/64})
    {
        int co = t & 31, q = t >> 5;
        float* ob = out + (size_t)(b * 64 + m) * 131072 + tile * 512;
        for (int i = 0; i < 128; i++) {
            int pair = i * 8 + q;                     // (d2,dd) in 64x16
            int d2 = pair >> 4, dd = pair & 15;
            float acc = 0.f;
            #pragma unroll
            for (int n = 0; n < 8; n++) {
                float2 v = Vs[(n * 16 + dd) * 32 + co];
                float2 e = tw[(n * d2) & 63];
                acc += v.x * e.x + v.y * e.y;         // Re(v * conj(tw)) = Re(v * e^{+i})
            }
            ob[(size_t)d2 * 2048 + dd * 32 + co] = acc;
        }
    }
}

// ---------------------------------------------------------------------------
extern "C" void kernel_launch(void* const* d_in, const int* in_sizes, int n_in,
                              void* d_out, int out_size) {
    const float* x  = (const float*)d_in[0];
    const float* wr = (const float*)d_in[1];
    const float* wi = (const float*)d_in[2];
    float* out = (float*)d_out;

    const int SM_F23 = (64 + 2048 + 8192) * sizeof(float2);   // 82432
    const int SM_INV = (64 + 2048 + 4096) * sizeof(float2);   // 49664
    cudaFuncSetAttribute(fwd_d2_mix, cudaFuncAttributeMaxDynamicSharedMemorySize, SM_F23);
    cudaFuncSetAttribute(inv_kernel, cudaFuncAttributeMaxDynamicSharedMemorySize, SM_INV);

    // Zero region: y[b, 8:64, :, :, :] == 0 exactly (D1 axis untouched by ifftn)
    for (int b = 0; b < 4; b++) {
        cudaMemsetAsync(out + ((size_t)b * 64 + 8) * 131072, 0,
                        (size_t)56 * 131072 * sizeof(float), 0);
    }

    prep_wsum<<<32, 256>>>(wr, wi);
    prep_M<<<8, 1024>>>();
    fwd_d3<<<2048, 256>>>(x);
    fwd_d2_mix<<<32, 256, SM_F23>>>();
    inv_kernel<<<128, 256, SM_INV>>>(out);
}

// round 2
// speedup vs baseline: 1.5325x; 1.5325x over previous
#include <cuda_runtime.h>
#include <math.h>

// B=4, D1=D2=D3=64, CIN=COUT=32, M1=M2=M3=8
// Pipeline (exact linear algebra, no full FFTs):
//   A[b,m,d2,p,c]  = sum_d3 x[b,m,d2,d3,c] e^{-2pi i p d3/64}      (m<8,p<8)
//   Bs[b,m,n,p,c]  = sum_d2 A e^{-2pi i n d2/64}                   (n<8)
//   U1[b,m,n,p,co] = sum_c Bs * M_p[c,co]
//   V -> y via inverse 8->64 DFTs on d3 then d2, take Re; y[:,8:]=0.

#define NB 4
#define NC 32
#define NM 8

__device__ float2 g_A  [NB*NM*64*NM*NC];   // [bm][d2][p][c]  4 MB
__device__ float2 g_U1 [NB*NM*NM*NM*NC];   // [bm][n][p][co]  512 KB
__device__ float2 g_Ws [NM*NC*NC];         // [p][k][o]
__device__ float2 g_M  [NM*NC*NC];         // [p][c][co]

// ---------------------------------------------------------------------------
// Prep 1: Wsum[p][k][o] = sum_{ij} (wr + i wi)[k][o][i][j][p]
// ---------------------------------------------------------------------------
__global__ void prep_wsum(const float* __restrict__ wr, const float* __restrict__ wi) {
    int t = blockIdx.x * blockDim.x + threadIdx.x;   // 8192 threads
    int p = t & 7;
    int o = (t >> 3) & 31;
    int k = t >> 8;
    float sr = 0.f, si = 0.f;
    int base = (k * 32 + o) * 512 + p;
    #pragma unroll 8
    for (int ij = 0; ij < 64; ij++) {
        sr += wr[base + ij * 8];
        si += wi[base + ij * 8];
    }
    g_Ws[(p * 32 + k) * 32 + o] = make_float2(sr, si);
}

// ---------------------------------------------------------------------------
// Prep 2: M_p = (1/131072) * IDFT32 o Wsum_p o DFT32  (one block per p)
// ---------------------------------------------------------------------------
__global__ void prep_M() {
    __shared__ float2 tw32[32];
    __shared__ float2 Ws[1024];
    __shared__ float2 P[1024];
    int p = blockIdx.x;
    int t = threadIdx.x;                              // 1024
    if (t < 32) {
        float s, c;
        sincospif(-(float)t / 16.0f, &s, &c);
        tw32[t] = make_float2(c, s);
    }
    Ws[t] = g_Ws[p * 1024 + t];
    __syncthreads();
    {
        int o = t & 31, c = t >> 5;
        float2 acc = make_float2(0.f, 0.f);
        #pragma unroll 8
        for (int k = 0; k < 32; k++) {
            float2 e = tw32[(k * c) & 31];
            float2 w = Ws[k * 32 + o];
            acc.x += e.x * w.x - e.y * w.y;
            acc.y += e.x * w.y + e.y * w.x;
        }
        P[c * 32 + o] = acc;
    }
    __syncthreads();
    {
        int co = t & 31, c = t >> 5;
        float2 acc = make_float2(0.f, 0.f);
        #pragma unroll 8
        for (int o = 0; o < 32; o++) {
            float2 e = tw32[(o * co) & 31];
            float2 v = P[c * 32 + o];
            acc.x += v.x * e.x + v.y * e.y;   // v * conj(e)
            acc.y += v.y * e.x - v.x * e.y;
        }
        const float scale = 1.0f / 131072.0f;
        g_M[(p * 32 + c) * 32 + co] = make_float2(acc.x * scale, acc.y * scale);
    }
}

// ---------------------------------------------------------------------------
// F1 + zero-fill: blocks [0,2048) do d3 forward DFT (64 -> 8 modes), one block
// per (b,m,d2). Blocks [2048,3072) zero-fill y[:, 8:64] (117 MB) in parallel.
// ---------------------------------------------------------------------------
__global__ void fwd_d3(const float* __restrict__ x, float* __restrict__ out) {
    int t = threadIdx.x;                              // 256
    if (blockIdx.x >= 2048) {
        // zero-fill region: out[b, 8:64, :, :, :] == 0 exactly
        int zb = blockIdx.x - 2048;                   // 0..1023
        float4* o4 = (float4*)out;
        const float4 z = make_float4(0.f, 0.f, 0.f, 0.f);
        #pragma unroll
        for (int b = 0; b < 4; b++) {
            size_t base = ((size_t)(b * 64 + 8)) * 32768;   // float4 units
            size_t g = (size_t)zb * 256 + t;
            #pragma unroll
            for (int i = 0; i < 7; i++)                      // 7*262144 = 1835008
                o4[base + g + (size_t)i * 262144] = z;
        }
        return;
    }
    __shared__ float  xs[2048];
    __shared__ float2 tw[64];
    if (t < 64) {
        float s, c;
        sincospif(-(float)t / 32.0f, &s, &c);         // e^{-2pi i t/64}
        tw[t] = make_float2(c, s);
    }
    int blk = blockIdx.x;                             // (b*8+m)*64 + d2
    int bm = blk >> 6;
    int d2 = blk & 63;
    int b = bm >> 3, m = bm & 7;
    const float4* xin = (const float4*)(x + ((size_t)(b * 64 + m) * 64 + d2) * 2048);
    float4* xs4 = (float4*)xs;
    xs4[t]       = xin[t];
    xs4[t + 256] = xin[t + 256];
    __syncthreads();
    int p = t >> 5, c = t & 31;
    float ar = 0.f, ai = 0.f;
    #pragma unroll 8
    for (int d3 = 0; d3 < 64; d3++) {
        float v = xs[d3 * 32 + c];
        float2 e = tw[(p * d3) & 63];
        ar += v * e.x;
        ai += v * e.y;
    }
    g_A[(size_t)blk * 256 + t] = make_float2(ar, ai);
}

// ---------------------------------------------------------------------------
// F2+F3 fused: d2 forward DFT (64 -> 8 modes) + channel mix via M_p.
// One block per (bm, p). 256 blocks, 256 threads.
// ---------------------------------------------------------------------------
__global__ void fwd_d2_mix() {
    __shared__ float2 tw[64];
    __shared__ float2 As[64 * 32];   // [d2][c] 16 KB
    __shared__ float2 Ms[32 * 32];   // [c][co]  8 KB
    __shared__ float2 Bs[8 * 32];    // [n][c]   2 KB
    int t = threadIdx.x;
    int blk = blockIdx.x;
    int bm = blk >> 3, p = blk & 7;
    if (t < 64) {
        float s, c;
        sincospif(-(float)t / 32.0f, &s, &c);
        tw[t] = make_float2(c, s);
    }
    {   // stage M_p (1024 float2 = 512 float4)
        const float4* msrc = (const float4*)(g_M + p * 1024);
        float4* mdst = (float4*)Ms;
        mdst[t]       = msrc[t];
        mdst[t + 256] = msrc[t + 256];
    }
    {   // stage A slice: g_A[bm][d2][p][c] -> As[d2][c]
        const float4* asrc = (const float4*)(g_A + (size_t)bm * 16384 + p * 32);
        float4* adst = (float4*)As;
        #pragma unroll
        for (int i = 0; i < 4; i++) {
            int idx = i * 256 + t;                    // 1024 float4
            int d2 = idx >> 4, j = idx & 15;
            adst[idx] = asrc[(size_t)d2 * 128 + j];
        }
    }
    __syncthreads();
    int n = t >> 5, c = t & 31;
    float2 acc = make_float2(0.f, 0.f);
    #pragma unroll 8
    for (int d2 = 0; d2 < 64; d2++) {
        float2 a = As[d2 * 32 + c];
        float2 e = tw[(n * d2) & 63];
        acc.x += a.x * e.x - a.y * e.y;
        acc.y += a.x * e.y + a.y * e.x;
    }
    Bs[n * 32 + c] = acc;
    __syncthreads();
    // mix: U1[bm][n][p][co] = sum_c Bs[n][c] * Ms[c][co]
    int co = c;
    float2 u = make_float2(0.f, 0.f);
    #pragma unroll 8
    for (int cc = 0; cc < 32; cc++) {
        float2 bv = Bs[n * 32 + cc];                  // warp broadcast
        float2 mv = Ms[cc * 32 + co];
        u.x += bv.x * mv.x - bv.y * mv.y;
        u.y += bv.x * mv.y + bv.y * mv.x;
    }
    g_U1[(size_t)bm * 2048 + (n * 8 + p) * 32 + co] = u;
}

// ---------------------------------------------------------------------------
// I1+I2 fused: d3 inverse (8 modes -> 64) + d2 inverse (8 modes -> 64) + Re.
// One block per (bm, d3-tile of 8). 256 blocks, 256 threads.
// ---------------------------------------------------------------------------
__global__ void inv_kernel(float* __restrict__ out) {
    __shared__ float2 tw[64];
    __shared__ float2 Us[8 * 8 * 32];   // [n][p][co] 16 KB
    __shared__ float2 Vs[8 * 8 * 32];   // [n][dd][co] 16 KB
    int t = threadIdx.x;
    int blk = blockIdx.x;               // bm*8 + tile
    int bm = blk >> 3;
    int tile = blk & 7;
    int b = bm >> 3, m = bm & 7;
    if (t < 64) {
        float s, c;
        sincospif(-(float)t / 32.0f, &s, &c);         // e^{-2pi i t/64}
        tw[t] = make_float2(c, s);
    }
    {   // stage U1[bm] slice (2048 float2 = 1024 float4)
        const float4* us = (const float4*)(g_U1 + (size_t)bm * 2048);
        float4* ud = (float4*)Us;
        #pragma unroll
        for (int i = 0; i < 4; i++) ud[t + i * 256] = us[t + i * 256];
    }
    __syncthreads();
    int co = t & 31, r = t >> 5;        // r in 0..7
    // phase 1: V[n][dd][co] = sum_p Us[n][p][co] * e^{+2pi i p d3/64}
    #pragma unroll
    for (int i = 0; i < 8; i++) {
        int pair = i * 8 + r;           // (n,dd) in 8x8
        int n = pair >> 3, dd = pair & 7;
        int d3 = tile * 8 + dd;
        float2 acc = make_float2(0.f, 0.f);
        #pragma unroll
        for (int p = 0; p < 8; p++) {
            float2 u = Us[(n * 8 + p) * 32 + co];
            float2 e = tw[(p * d3) & 63];             // conj => e^{+i}
            acc.x += u.x * e.x + u.y * e.y;
            acc.y += u.y * e.x - u.x * e.y;
        }
        Vs[(n * 8 + dd) * 32 + co] = acc;
    }
    __syncthreads();
    // phase 2: y[d2][d3][co] = sum_n Re(Vs[n][dd][co] * e^{+2pi i n d2/64})
    float* ob = out + (size_t)(b * 64 + m) * 131072 + tile * 256;
    #pragma unroll 4
    for (int i = 0; i < 64; i++) {
        int pair = i * 8 + r;           // (d2,dd) in 64x8
        int d2 = pair >> 3, dd = pair & 7;
        float acc = 0.f;
        #pragma unroll
        for (int n = 0; n < 8; n++) {
            float2 v = Vs[(n * 8 + dd) * 32 + co];
            float2 e = tw[(n * d2) & 63];
            acc += v.x * e.x + v.y * e.y;             // Re(v * e^{+i})
        }
        ob[(size_t)d2 * 2048 + dd * 32 + co] = acc;
    }
}

// ---------------------------------------------------------------------------
extern "C" void kernel_launch(void* const* d_in, const int* in_sizes, int n_in,
                              void* d_out, int out_size) {
    const float* x  = (const float*)d_in[0];
    const float* wr = (const float*)d_in[1];
    const float* wi = (const float*)d_in[2];
    float* out = (float*)d_out;

    prep_wsum<<<32, 256>>>(wr, wi);
    prep_M<<<8, 1024>>>();
    fwd_d3<<<3072, 256>>>(x, out);     // 2048 DFT blocks + 1024 zero-fill blocks
    fwd_d2_mix<<<256, 256>>>();
    inv_kernel<<<256, 256>>>(out);
}

// round 3
// speedup vs baseline: 1.9130x; 1.2482x over previous
#include <cuda_runtime.h>
#include <math.h>

// B=4, D1=D2=D3=64, CIN=COUT=32, M1=M2=M3=8
// Exact linear-algebra pipeline (no full FFTs):
//   A[bm,d2,p,c]  = sum_d3 x[bm,d2,d3,c] e^{-2pi i p d3/64}   (m<8,p<8)
//   Bs[bm,n,p,c]  = sum_d2 A e^{-2pi i n d2/64}               (n<8)
//   U1[bm,n,p,co] = sum_c Bs * M_p[c,co]
//   y via inverse 8->64 DFTs on d3 then d2, Re part; y[:,8:]=0 exactly.
// The 117MB zero region is written by extra blocks spread across all kernels.

#define NB 4
#define NC 32
#define NM 8

#define ZREG 1835008ull           // float4 per zero region (one per b)
#define Z1 1835008ull             // fwd_d3 share end
#define Z2 2935808ull             // prep_M share end
#define Z3 5137920ull             // d2mix share end
#define Z4 7340032ull             // total

__device__ float2 g_A  [NB*NM*64*NM*NC];   // [bm][d2][p][c]  4 MB
__device__ float2 g_U1 [NB*NM*NM*NM*NC];   // [bm][n][p][co]  512 KB
__device__ float2 g_Ws [NM*NC*NC];         // [p][k][o]
__device__ float2 g_M  [NM*NC*NC];         // [p][c][co]

// Zero-fill helper: grid-stride over float4 indices [lo,hi) of the flattened
// zero region (4 regions of ZREG float4: out[b, 8:64, :, :, :]).
__device__ __forceinline__ void zero_range(float4* o4, size_t lo, size_t hi,
                                           int zb, int nzb, int nthreads, int t) {
    const float4 z = make_float4(0.f, 0.f, 0.f, 0.f);
    size_t step = (size_t)nzb * nthreads;
    #pragma unroll
    for (int b = 0; b < 4; b++) {
        size_t rlo = (size_t)b * ZREG;
        size_t rhi = rlo + ZREG;
        size_t s = lo > rlo ? lo : rlo;
        size_t e = hi < rhi ? hi : rhi;
        float4* base = o4 + (size_t)(b * 64 + 8) * 32768 - rlo;
        for (size_t i = s + (size_t)zb * nthreads + t; i < e; i += step)
            __stcs(base + i, z);
    }
}

// ---------------------------------------------------------------------------
// K1: blocks [0,2048): d3 forward DFT (64 -> 8 modes), one per (bm,d2).
//     blocks [2048,2080): Wsum[p][k][o] = sum_ij (wr+i wi)[k][o][i][j][p]
//     blocks [2080,2336): zero-fill share [0, Z1)
// ---------------------------------------------------------------------------
__global__ void fwd_d3(const float* __restrict__ x,
                       const float* __restrict__ wr, const float* __restrict__ wi,
                       float* __restrict__ out) {
    int t = threadIdx.x;                              // 256
    if (blockIdx.x >= 2080) {
        zero_range((float4*)out, 0, Z1, blockIdx.x - 2080, 256, 256, t);
        return;
    }
    if (blockIdx.x >= 2048) {
        int g = (blockIdx.x - 2048) * 256 + t;        // 0..8191
        int p = g & 7;
        int o = (g >> 3) & 31;
        int k = g >> 8;
        float sr = 0.f, si = 0.f;
        int base = (k * 32 + o) * 512 + p;
        #pragma unroll 8
        for (int ij = 0; ij < 64; ij++) {
            sr += wr[base + ij * 8];
            si += wi[base + ij * 8];
        }
        g_Ws[(p * 32 + k) * 32 + o] = make_float2(sr, si);
        return;
    }
    __shared__ float  xs[2048];
    __shared__ float2 tw[64];
    if (t < 64) {
        float s, c;
        sincospif(-(float)t / 32.0f, &s, &c);         // e^{-2pi i t/64}
        tw[t] = make_float2(c, s);
    }
    int blk = blockIdx.x;                             // (b*8+m)*64 + d2
    int bm = blk >> 6;
    int d2 = blk & 63;
    int b = bm >> 3, m = bm & 7;
    const float4* xin = (const float4*)(x + ((size_t)(b * 64 + m) * 64 + d2) * 2048);
    float4* xs4 = (float4*)xs;
    xs4[t]       = __ldcs(xin + t);
    xs4[t + 256] = __ldcs(xin + t + 256);
    __syncthreads();
    int p = t >> 5, c = t & 31;
    float ar = 0.f, ai = 0.f;
    #pragma unroll 8
    for (int d3 = 0; d3 < 64; d3++) {
        float v = xs[d3 * 32 + c];
        float2 e = tw[(p * d3) & 63];
        ar += v * e.x;
        ai += v * e.y;
    }
    g_A[(size_t)blk * 256 + t] = make_float2(ar, ai);
}

// ---------------------------------------------------------------------------
// K2: blocks [0,8): M_p = (1/131072) IDFT32 o Wsum_p o DFT32.
//     blocks [8,136): zero-fill share [Z1, Z2).   blockDim = 1024
// ---------------------------------------------------------------------------
__global__ void prep_M(float* __restrict__ out) {
    int t = threadIdx.x;                              // 1024
    if (blockIdx.x >= 8) {
        zero_range((float4*)out, Z1, Z2, blockIdx.x - 8, 128, 1024, t);
        return;
    }
    __shared__ float2 tw32[32];
    __shared__ float2 Ws[1024];
    __shared__ float2 P[1024];
    int p = blockIdx.x;
    if (t < 32) {
        float s, c;
        sincospif(-(float)t / 16.0f, &s, &c);
        tw32[t] = make_float2(c, s);
    }
    Ws[t] = g_Ws[p * 1024 + t];
    __syncthreads();
    {
        int o = t & 31, c = t >> 5;
        float2 acc = make_float2(0.f, 0.f);
        #pragma unroll 8
        for (int k = 0; k < 32; k++) {
            float2 e = tw32[(k * c) & 31];
            float2 w = Ws[k * 32 + o];
            acc.x += e.x * w.x - e.y * w.y;
            acc.y += e.x * w.y + e.y * w.x;
        }
        P[c * 32 + o] = acc;
    }
    __syncthreads();
    {
        int co = t & 31, c = t >> 5;
        float2 acc = make_float2(0.f, 0.f);
        #pragma unroll 8
        for (int o = 0; o < 32; o++) {
            float2 e = tw32[(o * co) & 31];
            float2 v = P[c * 32 + o];
            acc.x += v.x * e.x + v.y * e.y;   // v * conj(e)
            acc.y += v.y * e.x - v.x * e.y;
        }
        const float scale = 1.0f / 131072.0f;
        g_M[(p * 32 + c) * 32 + co] = make_float2(acc.x * scale, acc.y * scale);
    }
}

// ---------------------------------------------------------------------------
// K3: blocks [0,256): d2 forward DFT + channel mix, one per (bm,p).
//     blocks [256,512): zero-fill share [Z2, Z3).
// ---------------------------------------------------------------------------
__global__ void fwd_d2_mix(float* __restrict__ out) {
    int t = threadIdx.x;
    if (blockIdx.x >= 256) {
        zero_range((float4*)out, Z2, Z3, blockIdx.x - 256, 256, 256, t);
        return;
    }
    __shared__ float2 tw[64];
    __shared__ float2 As[64 * 32];   // [d2][c] 16 KB
    __shared__ float2 Ms[32 * 32];   // [c][co]  8 KB
    __shared__ float2 Bs[8 * 32];    // [n][c]   2 KB
    int blk = blockIdx.x;
    int bm = blk >> 3, p = blk & 7;
    if (t < 64) {
        float s, c;
        sincospif(-(float)t / 32.0f, &s, &c);
        tw[t] = make_float2(c, s);
    }
    {   // stage M_p
        const float4* msrc = (const float4*)(g_M + p * 1024);
        float4* mdst = (float4*)Ms;
        mdst[t]       = msrc[t];
        mdst[t + 256] = msrc[t + 256];
    }
    {   // stage A slice: g_A[bm][d2][p][c] -> As[d2][c]
        const float4* asrc = (const float4*)(g_A + (size_t)bm * 16384 + p * 32);
        float4* adst = (float4*)As;
        #pragma unroll
        for (int i = 0; i < 4; i++) {
            int idx = i * 256 + t;
            int d2 = idx >> 4, j = idx & 15;
            adst[idx] = asrc[(size_t)d2 * 128 + j];
        }
    }
    __syncthreads();
    int n = t >> 5, c = t & 31;
    float2 acc = make_float2(0.f, 0.f);
    #pragma unroll 8
    for (int d2 = 0; d2 < 64; d2++) {
        float2 a = As[d2 * 32 + c];
        float2 e = tw[(n * d2) & 63];
        acc.x += a.x * e.x - a.y * e.y;
        acc.y += a.x * e.y + a.y * e.x;
    }
    Bs[n * 32 + c] = acc;
    __syncthreads();
    int co = c;
    float2 u = make_float2(0.f, 0.f);
    #pragma unroll 8
    for (int cc = 0; cc < 32; cc++) {
        float2 bv = Bs[n * 32 + cc];                  // warp broadcast
        float2 mv = Ms[cc * 32 + co];
        u.x += bv.x * mv.x - bv.y * mv.y;
        u.y += bv.x * mv.y + bv.y * mv.x;
    }
    g_U1[(size_t)bm * 2048 + (n * 8 + p) * 32 + co] = u;
}

// ---------------------------------------------------------------------------
// K4: blocks [0,256): inverse d3 (8->64) + inverse d2 (8->64) + Re,
//     one per (bm, d3-tile of 8). blocks [256,512): zero share [Z3, Z4).
// ---------------------------------------------------------------------------
__global__ void inv_kernel(float* __restrict__ out) {
    int t = threadIdx.x;
    if (blockIdx.x >= 256) {
        zero_range((float4*)out, Z3, Z4, blockIdx.x - 256, 256, 256, t);
        return;
    }
    __shared__ float2 tw[64];
    __shared__ float2 Us[8 * 8 * 32];   // [n][p][co] 16 KB
    __shared__ float2 Vs[8 * 8 * 32];   // [n][dd][co] 16 KB
    int blk = blockIdx.x;               // bm*8 + tile
    int bm = blk >> 3;
    int tile = blk & 7;
    int b = bm >> 3, m = bm & 7;
    if (t < 64) {
        float s, c;
        sincospif(-(float)t / 32.0f, &s, &c);         // e^{-2pi i t/64}
        tw[t] = make_float2(c, s);
    }
    {   // stage U1[bm] slice
        const float4* us = (const float4*)(g_U1 + (size_t)bm * 2048);
        float4* ud = (float4*)Us;
        #pragma unroll
        for (int i = 0; i < 4; i++) ud[t + i * 256] = us[t + i * 256];
    }
    __syncthreads();
    int co = t & 31, dd = t >> 5;       // dd in 0..7 (this thread's d3-within-tile)
    // phase 1: V[n][dd][co] = sum_p Us[n][p][co] * e^{+2pi i p d3/64}
    int d3 = tile * 8 + dd;
    #pragma unroll
    for (int n = 0; n < 8; n++) {
        float2 acc = make_float2(0.f, 0.f);
        #pragma unroll
        for (int p = 0; p < 8; p++) {
            float2 u = Us[(n * 8 + p) * 32 + co];
            float2 e = tw[(p * d3) & 63];             // conj => e^{+i}
            acc.x += u.x * e.x + u.y * e.y;
            acc.y += u.y * e.x - u.x * e.y;
        }
        Vs[(n * 8 + dd) * 32 + co] = acc;
    }
    __syncthreads();
    // phase 2: register-cache Vs (loop-invariant across d2), then sweep d2.
    float2 vreg[8];
    #pragma unroll
    for (int n = 0; n < 8; n++) vreg[n] = Vs[(n * 8 + dd) * 32 + co];
    float* ob = out + (size_t)(b * 64 + m) * 131072 + tile * 256 + dd * 32 + co;
    #pragma unroll 8
    for (int d2 = 0; d2 < 64; d2++) {
        float acc = 0.f;
        #pragma unroll
        for (int n = 0; n < 8; n++) {
            float2 e = tw[(n * d2) & 63];
            acc += vreg[n].x * e.x + vreg[n].y * e.y; // Re(v * e^{+i})
        }
        __stcs(ob + (size_t)d2 * 2048, acc);
    }
}

// ---------------------------------------------------------------------------
extern "C" void kernel_launch(void* const* d_in, const int* in_sizes, int n_in,
                              void* d_out, int out_size) {
    const float* x  = (const float*)d_in[0];
    const float* wr = (const float*)d_in[1];
    const float* wi = (const float*)d_in[2];
    float* out = (float*)d_out;

    fwd_d3<<<2336, 256>>>(x, wr, wi, out);   // DFT + wsum + zeros
    prep_M<<<136, 1024>>>(out);              // M build + zeros
    fwd_d2_mix<<<512, 256>>>(out);           // DFT+mix + zeros
    inv_kernel<<<512, 256>>>(out);           // inverse + zeros
}